// round 14
// baseline (speedup 1.0000x reference)
#include <cuda_runtime.h>
#include <math.h>
#include <stdint.h>

// ---------------------------------------------------------------------------
// SearchNet: cosine similarity (1 query x N database rows) + top-k
//   out[0..k-1]  = top-k values (desc, ties -> lower index first)
//   out[k..2k-1] = top-k indices (as float)
// ---------------------------------------------------------------------------

#define DIMS        512
#define MAXN        500000
#define HIST_BINS   4096
#define CAP         4096
#define EPSF        1e-8f

__device__ float    g_qn[DIMS];
__device__ float    g_sims[MAXN];
__device__ int      g_hist1[HIST_BINS];
__device__ int      g_hist2[HIST_BINS];
__device__ int      g_counter;
__device__ int      g_b1;
__device__ int      g_cntgt;      // count of keys strictly above bin b1
__device__ unsigned g_thresh;     // select all keys >= g_thresh
__device__ unsigned g_candKey[CAP];
__device__ int      g_candIdx[CAP];
__device__ float    g_candVal[CAP];

__device__ __forceinline__ unsigned mono(float f) {
    unsigned u = __float_as_uint(f);
    return (u & 0x80000000u) ? ~u : (u | 0x80000000u);
}

// ---- K1: normalize query, zero scratch -------------------------------------
__global__ void k_init(const float* __restrict__ q, int D) {
    __shared__ float red[512];
    int t = threadIdx.x;
    float v = (t < D) ? q[t] : 0.0f;
    red[t] = v * v;
    __syncthreads();
    #pragma unroll
    for (int s = 256; s > 0; s >>= 1) {
        if (t < s) red[t] += red[t + s];
        __syncthreads();
    }
    float inv = 1.0f / fmaxf(sqrtf(red[0]), EPSF);
    if (t < D) g_qn[t] = v * inv;
    for (int i = t; i < HIST_BINS; i += 512) { g_hist1[i] = 0; g_hist2[i] = 0; }
    if (t == 0) { g_counter = 0; g_b1 = 0; g_cntgt = 0; g_thresh = 0; }
}

// ---- K2: the 1 GB streaming pass (TWO rows per warp, MLP_p1 = 8) -----------
__global__ void __launch_bounds__(512) k_sims(const float* __restrict__ db, int N) {
    __shared__ float4 qs[DIMS / 4];
    int t = threadIdx.x;
    if (t < DIMS / 4) qs[t] = reinterpret_cast<const float4*>(g_qn)[t];
    __syncthreads();

    int warp = (blockIdx.x * 512 + t) >> 5;
    int lane = t & 31;
    int r0   = warp * 2;
    if (r0 >= N) return;
    bool has1 = (r0 + 1 < N);

    const float4* row0 = reinterpret_cast<const float4*>(db) + (size_t)r0 * (DIMS / 4);
    const float4* row1 = row0 + (DIMS / 4);

    float4 a[4], b[4];
    #pragma unroll
    for (int i = 0; i < 4; i++) a[i] = __ldcs(&row0[lane + 32 * i]);
    #pragma unroll
    for (int i = 0; i < 4; i++)
        b[i] = has1 ? __ldcs(&row1[lane + 32 * i]) : make_float4(0.f, 0.f, 0.f, 0.f);

    float d0 = 0.f, n0 = 0.f, d1 = 0.f, n1 = 0.f;
    #pragma unroll
    for (int i = 0; i < 4; i++) {
        float4 q = qs[lane + 32 * i];
        d0 += a[i].x * q.x + a[i].y * q.y + a[i].z * q.z + a[i].w * q.w;
        n0 += a[i].x * a[i].x + a[i].y * a[i].y + a[i].z * a[i].z + a[i].w * a[i].w;
        d1 += b[i].x * q.x + b[i].y * q.y + b[i].z * q.z + b[i].w * q.w;
        n1 += b[i].x * b[i].x + b[i].y * b[i].y + b[i].z * b[i].z + b[i].w * b[i].w;
    }
    #pragma unroll
    for (int o = 16; o > 0; o >>= 1) {
        d0 += __shfl_down_sync(0xffffffffu, d0, o);
        n0 += __shfl_down_sync(0xffffffffu, n0, o);
        d1 += __shfl_down_sync(0xffffffffu, d1, o);
        n1 += __shfl_down_sync(0xffffffffu, n1, o);
    }
    if (lane == 0) {
        g_sims[r0] = d0 / fmaxf(sqrtf(n0), EPSF);
        if (has1) g_sims[r0 + 1] = d1 / fmaxf(sqrtf(n1), EPSF);
    }
}

// ---- K3: histogram on top 12 bits (L2-hot pass, privatized) ----------------
__global__ void __launch_bounds__(256) k_hist1(int N) {
    __shared__ int h[HIST_BINS];
    for (int i = threadIdx.x; i < HIST_BINS; i += 256) h[i] = 0;
    __syncthreads();
    for (int i = blockIdx.x * 256 + threadIdx.x; i < N; i += gridDim.x * 256)
        atomicAdd(&h[mono(g_sims[i]) >> 20], 1);
    __syncthreads();
    for (int i = threadIdx.x; i < HIST_BINS; i += 256) {
        int c = h[i];
        if (c) atomicAdd(&g_hist1[i], c);
    }
}

// ---- Parallel descending-cumulative scan (one 1024-thread block) -----------
// Finds largest bin b with suffix_sum(b) >= k; writes b and the count strictly
// above b into out_bin / out_above.
__device__ void scan_desc(const int* __restrict__ hist, int k,
                          int* out_bin, int* out_above) {
    __shared__ int sfx[1024];
    __shared__ int s_acc;
    __shared__ int s_done;
    if (threadIdx.x == 0) { s_acc = 0; s_done = 0; }
    __syncthreads();

    for (int base = HIST_BINS - 1024; base >= 0; base -= 1024) {
        if (s_done) return;
        sfx[threadIdx.x] = hist[base + threadIdx.x];
        __syncthreads();
        // inclusive suffix-sum (Hillis-Steele, reversed)
        #pragma unroll
        for (int o = 1; o < 1024; o <<= 1) {
            int v = (threadIdx.x + o < 1024) ? sfx[threadIdx.x + o] : 0;
            __syncthreads();
            sfx[threadIdx.x] += v;
            __syncthreads();
        }
        int acc = s_acc;
        int chunkTotal = sfx[0];
        if (acc + chunkTotal >= k) {
            int above = (threadIdx.x + 1 < 1024) ? sfx[threadIdx.x + 1] : 0;
            if (acc + sfx[threadIdx.x] >= k && acc + above < k) {
                *out_bin   = base + threadIdx.x;
                *out_above = acc + above;
            }
            __syncthreads();
            if (threadIdx.x == 0) s_done = 1;
        } else {
            __syncthreads();
            if (threadIdx.x == 0) s_acc = acc + chunkTotal;
        }
        __syncthreads();
    }
}

__global__ void __launch_bounds__(1024) k_scan1(const int* topk) {
    int k = topk ? *topk : 100;
    if (k < 1) k = 1;
    scan_desc(g_hist1, k, &g_b1, &g_cntgt);
}

// ---- K5: refine — histogram next 12 bits within bin b1 ---------------------
__global__ void __launch_bounds__(256) k_hist2(int N) {
    unsigned b1 = (unsigned)g_b1;
    for (int i = blockIdx.x * 256 + threadIdx.x; i < N; i += gridDim.x * 256) {
        unsigned key = mono(g_sims[i]);
        if ((key >> 20) == b1)
            atomicAdd(&g_hist2[(key >> 8) & 0xFFFu], 1);
    }
}

__global__ void __launch_bounds__(1024) k_scan2(const int* topk) {
    int k = topk ? *topk : 100;
    if (k < 1) k = 1;
    int k2 = k - g_cntgt;
    if (k2 < 1) k2 = 1;
    __shared__ int b2_s, dummy;
    if (threadIdx.x == 0) { b2_s = 0; dummy = 0; }
    __syncthreads();
    scan_desc(g_hist2, k2, &b2_s, &dummy);
    __syncthreads();
    if (threadIdx.x == 0)
        g_thresh = ((unsigned)g_b1 << 20) | ((unsigned)b2_s << 8);
}

// ---- K7: gather survivors (expected ~100-300, cap 4096) --------------------
__global__ void __launch_bounds__(256) k_gather(int N) {
    unsigned th = g_thresh;
    for (int i = blockIdx.x * 256 + threadIdx.x; i < N; i += gridDim.x * 256) {
        float v = g_sims[i];
        unsigned key = mono(v);
        if (key >= th) {
            int p = atomicAdd(&g_counter, 1);
            if (p < CAP) {
                g_candKey[p] = key;
                g_candIdx[p] = i;
                g_candVal[p] = v;
            }
        }
    }
}

// ---- K8: exact rank selection among survivors, write output ----------------
__global__ void __launch_bounds__(1024) k_final(const int* topk,
                                                float* __restrict__ out,
                                                int out_size) {
    __shared__ unsigned sk[CAP];
    __shared__ int      si[CAP];
    int n = g_counter;
    if (n > CAP) n = CAP;
    int k = topk ? *topk : 100;

    for (int i = threadIdx.x; i < n; i += 1024) {
        sk[i] = g_candKey[i];
        si[i] = g_candIdx[i];
    }
    __syncthreads();

    for (int i = threadIdx.x; i < n; i += 1024) {
        unsigned mk = sk[i];
        int      mi = si[i];
        int r = 0;
        for (int j = 0; j < n; j++) {
            unsigned kj = sk[j];
            r += (kj > mk) || (kj == mk && si[j] < mi);
        }
        if (r < k) {
            if (r < out_size)     out[r]     = g_candVal[i];
            if (k + r < out_size) out[k + r] = (float)mi;
        }
    }
}

// ---------------------------------------------------------------------------
extern "C" void kernel_launch(void* const* d_in, const int* in_sizes, int n_in,
                              void* d_out, int out_size) {
    const float* q    = (const float*)d_in[0];
    const float* db   = (const float*)d_in[1];
    const int*   topk = (n_in >= 3) ? (const int*)d_in[2] : nullptr;

    int D = in_sizes[0];               // 512
    int N = in_sizes[1] / D;           // 500000
    if (N > MAXN) N = MAXN;

    k_init<<<1, 512>>>(q, D);

    // 2 rows per warp, 16 warps per block -> 32 rows per block
    int blocks = (N + 31) / 32;
    k_sims<<<blocks, 512>>>(db, N);

    k_hist1<<<1024, 256>>>(N);
    k_scan1<<<1, 1024>>>(topk);
    k_hist2<<<1024, 256>>>(N);
    k_scan2<<<1, 1024>>>(topk);
    k_gather<<<1024, 256>>>(N);
    k_final<<<1, 1024>>>(topk, (float*)d_out, out_size);
}

// round 15
// speedup vs baseline: 1.0041x; 1.0041x over previous
#include <cuda_runtime.h>
#include <math.h>
#include <stdint.h>

// ---------------------------------------------------------------------------
// SearchNet: cosine similarity (1 query x N database rows) + top-k
//   out[0..k-1]  = top-k values (desc, ties -> lower index first)
//   out[k..2k-1] = top-k indices (as float)
// ---------------------------------------------------------------------------

#define DIMS        512
#define MAXN        500000
#define HIST_BINS   4096
#define CAP         4096
#define EPSF        1e-8f

__device__ float    g_qn[DIMS];
__device__ float    g_sims[MAXN];
__device__ int      g_hist1[HIST_BINS];
__device__ int      g_hist2[HIST_BINS];
__device__ int      g_counter;
__device__ int      g_b1;
__device__ int      g_cntgt;      // count of keys strictly above bin b1
__device__ unsigned g_thresh;     // select all keys >= g_thresh
__device__ unsigned g_candKey[CAP];
__device__ int      g_candIdx[CAP];
__device__ float    g_candVal[CAP];

__device__ __forceinline__ unsigned mono(float f) {
    unsigned u = __float_as_uint(f);
    return (u & 0x80000000u) ? ~u : (u | 0x80000000u);
}

// ---- K1: normalize query, zero scratch -------------------------------------
__global__ void k_init(const float* __restrict__ q, int D) {
    __shared__ float red[512];
    int t = threadIdx.x;
    float v = (t < D) ? q[t] : 0.0f;
    red[t] = v * v;
    __syncthreads();
    #pragma unroll
    for (int s = 256; s > 0; s >>= 1) {
        if (t < s) red[t] += red[t + s];
        __syncthreads();
    }
    float inv = 1.0f / fmaxf(sqrtf(red[0]), EPSF);
    if (t < D) g_qn[t] = v * inv;
    for (int i = t; i < HIST_BINS; i += 512) { g_hist1[i] = 0; g_hist2[i] = 0; }
    if (t == 0) { g_counter = 0; g_b1 = 0; g_cntgt = 0; g_thresh = 0; }
}

// ---- K2: the 1 GB streaming pass (TWO rows per warp, MLP_p1 = 8) -----------
__global__ void __launch_bounds__(512) k_sims(const float* __restrict__ db, int N) {
    __shared__ float4 qs[DIMS / 4];
    int t = threadIdx.x;
    if (t < DIMS / 4) qs[t] = reinterpret_cast<const float4*>(g_qn)[t];
    __syncthreads();

    int warp = (blockIdx.x * 512 + t) >> 5;
    int lane = t & 31;
    int r0   = warp * 2;
    if (r0 >= N) return;
    bool has1 = (r0 + 1 < N);

    const float4* row0 = reinterpret_cast<const float4*>(db) + (size_t)r0 * (DIMS / 4);
    const float4* row1 = row0 + (DIMS / 4);

    float4 a[4], b[4];
    #pragma unroll
    for (int i = 0; i < 4; i++) a[i] = __ldcs(&row0[lane + 32 * i]);
    #pragma unroll
    for (int i = 0; i < 4; i++)
        b[i] = has1 ? __ldcs(&row1[lane + 32 * i]) : make_float4(0.f, 0.f, 0.f, 0.f);

    float d0 = 0.f, n0 = 0.f, d1 = 0.f, n1 = 0.f;
    #pragma unroll
    for (int i = 0; i < 4; i++) {
        float4 q = qs[lane + 32 * i];
        d0 += a[i].x * q.x + a[i].y * q.y + a[i].z * q.z + a[i].w * q.w;
        n0 += a[i].x * a[i].x + a[i].y * a[i].y + a[i].z * a[i].z + a[i].w * a[i].w;
        d1 += b[i].x * q.x + b[i].y * q.y + b[i].z * q.z + b[i].w * q.w;
        n1 += b[i].x * b[i].x + b[i].y * b[i].y + b[i].z * b[i].z + b[i].w * b[i].w;
    }
    #pragma unroll
    for (int o = 16; o > 0; o >>= 1) {
        d0 += __shfl_down_sync(0xffffffffu, d0, o);
        n0 += __shfl_down_sync(0xffffffffu, n0, o);
        d1 += __shfl_down_sync(0xffffffffu, d1, o);
        n1 += __shfl_down_sync(0xffffffffu, n1, o);
    }
    if (lane == 0) {
        g_sims[r0] = d0 / fmaxf(sqrtf(n0), EPSF);
        if (has1) g_sims[r0 + 1] = d1 / fmaxf(sqrtf(n1), EPSF);
    }
}

// ---- K3: histogram on top 12 bits (L2-hot pass, privatized) ----------------
__global__ void __launch_bounds__(256) k_hist1(int N) {
    __shared__ int h[HIST_BINS];
    for (int i = threadIdx.x; i < HIST_BINS; i += 256) h[i] = 0;
    __syncthreads();
    for (int i = blockIdx.x * 256 + threadIdx.x; i < N; i += gridDim.x * 256)
        atomicAdd(&h[mono(g_sims[i]) >> 20], 1);
    __syncthreads();
    for (int i = threadIdx.x; i < HIST_BINS; i += 256) {
        int c = h[i];
        if (c) atomicAdd(&g_hist1[i], c);
    }
}

// ---- Parallel descending-cumulative scan (one 1024-thread block) -----------
// Finds largest bin b with suffix_sum(b) >= k; writes b and the count strictly
// above b into out_bin / out_above.
__device__ void scan_desc(const int* __restrict__ hist, int k,
                          int* out_bin, int* out_above) {
    __shared__ int sfx[1024];
    __shared__ int s_acc;
    __shared__ int s_done;
    if (threadIdx.x == 0) { s_acc = 0; s_done = 0; }
    __syncthreads();

    for (int base = HIST_BINS - 1024; base >= 0; base -= 1024) {
        if (s_done) return;
        sfx[threadIdx.x] = hist[base + threadIdx.x];
        __syncthreads();
        // inclusive suffix-sum (Hillis-Steele, reversed)
        #pragma unroll
        for (int o = 1; o < 1024; o <<= 1) {
            int v = (threadIdx.x + o < 1024) ? sfx[threadIdx.x + o] : 0;
            __syncthreads();
            sfx[threadIdx.x] += v;
            __syncthreads();
        }
        int acc = s_acc;
        int chunkTotal = sfx[0];
        if (acc + chunkTotal >= k) {
            int above = (threadIdx.x + 1 < 1024) ? sfx[threadIdx.x + 1] : 0;
            if (acc + sfx[threadIdx.x] >= k && acc + above < k) {
                *out_bin   = base + threadIdx.x;
                *out_above = acc + above;
            }
            __syncthreads();
            if (threadIdx.x == 0) s_done = 1;
        } else {
            __syncthreads();
            if (threadIdx.x == 0) s_acc = acc + chunkTotal;
        }
        __syncthreads();
    }
}

__global__ void __launch_bounds__(1024) k_scan1(const int* topk) {
    int k = topk ? *topk : 100;
    if (k < 1) k = 1;
    scan_desc(g_hist1, k, &g_b1, &g_cntgt);
}

// ---- K5: refine — histogram next 12 bits within bin b1 ---------------------
__global__ void __launch_bounds__(256) k_hist2(int N) {
    unsigned b1 = (unsigned)g_b1;
    for (int i = blockIdx.x * 256 + threadIdx.x; i < N; i += gridDim.x * 256) {
        unsigned key = mono(g_sims[i]);
        if ((key >> 20) == b1)
            atomicAdd(&g_hist2[(key >> 8) & 0xFFFu], 1);
    }
}

__global__ void __launch_bounds__(1024) k_scan2(const int* topk) {
    int k = topk ? *topk : 100;
    if (k < 1) k = 1;
    int k2 = k - g_cntgt;
    if (k2 < 1) k2 = 1;
    __shared__ int b2_s, dummy;
    if (threadIdx.x == 0) { b2_s = 0; dummy = 0; }
    __syncthreads();
    scan_desc(g_hist2, k2, &b2_s, &dummy);
    __syncthreads();
    if (threadIdx.x == 0)
        g_thresh = ((unsigned)g_b1 << 20) | ((unsigned)b2_s << 8);
}

// ---- K7: gather survivors (expected ~100-300, cap 4096) --------------------
__global__ void __launch_bounds__(256) k_gather(int N) {
    unsigned th = g_thresh;
    for (int i = blockIdx.x * 256 + threadIdx.x; i < N; i += gridDim.x * 256) {
        float v = g_sims[i];
        unsigned key = mono(v);
        if (key >= th) {
            int p = atomicAdd(&g_counter, 1);
            if (p < CAP) {
                g_candKey[p] = key;
                g_candIdx[p] = i;
                g_candVal[p] = v;
            }
        }
    }
}

// ---- K8: exact rank selection among survivors, write output ----------------
__global__ void __launch_bounds__(1024) k_final(const int* topk,
                                                float* __restrict__ out,
                                                int out_size) {
    __shared__ unsigned sk[CAP];
    __shared__ int      si[CAP];
    int n = g_counter;
    if (n > CAP) n = CAP;
    int k = topk ? *topk : 100;

    for (int i = threadIdx.x; i < n; i += 1024) {
        sk[i] = g_candKey[i];
        si[i] = g_candIdx[i];
    }
    __syncthreads();

    for (int i = threadIdx.x; i < n; i += 1024) {
        unsigned mk = sk[i];
        int      mi = si[i];
        int r = 0;
        for (int j = 0; j < n; j++) {
            unsigned kj = sk[j];
            r += (kj > mk) || (kj == mk && si[j] < mi);
        }
        if (r < k) {
            if (r < out_size)     out[r]     = g_candVal[i];
            if (k + r < out_size) out[k + r] = (float)mi;
        }
    }
}

// ---------------------------------------------------------------------------
extern "C" void kernel_launch(void* const* d_in, const int* in_sizes, int n_in,
                              void* d_out, int out_size) {
    const float* q    = (const float*)d_in[0];
    const float* db   = (const float*)d_in[1];
    const int*   topk = (n_in >= 3) ? (const int*)d_in[2] : nullptr;

    int D = in_sizes[0];               // 512
    int N = in_sizes[1] / D;           // 500000
    if (N > MAXN) N = MAXN;

    k_init<<<1, 512>>>(q, D);

    // 2 rows per warp, 16 warps per block -> 32 rows per block
    int blocks = (N + 31) / 32;
    k_sims<<<blocks, 512>>>(db, N);

    k_hist1<<<1024, 256>>>(N);
    k_scan1<<<1, 1024>>>(topk);
    k_hist2<<<1024, 256>>>(N);
    k_scan2<<<1, 1024>>>(topk);
    k_gather<<<1024, 256>>>(N);
    k_final<<<1, 1024>>>(topk, (float*)d_out, out_size);
}

// round 16
// speedup vs baseline: 1.0405x; 1.0362x over previous
#include <cuda_runtime.h>
#include <math.h>
#include <stdint.h>

// ---------------------------------------------------------------------------
// SearchNet: cosine similarity (1 query x N database rows) + top-k
//   out[0..k-1]  = top-k values (desc, ties -> lower index first)
//   out[k..2k-1] = top-k indices (as float)
//
// Pipeline (4 kernels):
//   k_init        : normalize query, zero 64K-bin histogram + counters
//   k_sims        : 1 GB stream; sims + fused 16-bit-key histogram (RED)
//   k_scan        : suffix-scan 65536 bins -> 16-bit threshold
//   k_gather_final: gather survivors; last block does exact rank select
// ---------------------------------------------------------------------------

#define DIMS        512
#define MAXN        500000
#define HBINS       65536
#define CAP         4096
#define EPSF        1e-8f

__device__ float    g_qn[DIMS];
__device__ float    g_sims[MAXN];
__device__ int      g_hist[HBINS];
__device__ int      g_counter;
__device__ int      g_done;
__device__ unsigned g_thresh;     // select all keys >= g_thresh
__device__ unsigned g_candKey[CAP];
__device__ int      g_candIdx[CAP];
__device__ float    g_candVal[CAP];

__device__ __forceinline__ unsigned mono(float f) {
    unsigned u = __float_as_uint(f);
    return (u & 0x80000000u) ? ~u : (u | 0x80000000u);
}

// ---- K1: normalize query, zero scratch (64 blocks) --------------------------
__global__ void __launch_bounds__(512) k_init(const float* __restrict__ q, int D) {
    // all blocks: zero the histogram
    for (int i = blockIdx.x * 512 + threadIdx.x; i < HBINS; i += gridDim.x * 512)
        g_hist[i] = 0;

    if (blockIdx.x != 0) return;
    __shared__ float red[512];
    int t = threadIdx.x;
    float v = (t < D) ? q[t] : 0.0f;
    red[t] = v * v;
    __syncthreads();
    #pragma unroll
    for (int s = 256; s > 0; s >>= 1) {
        if (t < s) red[t] += red[t + s];
        __syncthreads();
    }
    float inv = 1.0f / fmaxf(sqrtf(red[0]), EPSF);
    if (t < D) g_qn[t] = v * inv;
    if (t == 0) { g_counter = 0; g_done = 0; g_thresh = 0; }
}

// ---- K2: 1 GB streaming pass (2 rows/warp) + fused histogram ----------------
__global__ void __launch_bounds__(512) k_sims(const float* __restrict__ db, int N) {
    __shared__ float4 qs[DIMS / 4];
    int t = threadIdx.x;
    if (t < DIMS / 4) qs[t] = reinterpret_cast<const float4*>(g_qn)[t];
    __syncthreads();

    int warp = (blockIdx.x * 512 + t) >> 5;
    int lane = t & 31;
    int r0   = warp * 2;
    if (r0 >= N) return;
    bool has1 = (r0 + 1 < N);

    const float4* row0 = reinterpret_cast<const float4*>(db) + (size_t)r0 * (DIMS / 4);
    const float4* row1 = row0 + (DIMS / 4);

    float4 a[4], b[4];
    #pragma unroll
    for (int i = 0; i < 4; i++) a[i] = __ldcs(&row0[lane + 32 * i]);
    #pragma unroll
    for (int i = 0; i < 4; i++)
        b[i] = has1 ? __ldcs(&row1[lane + 32 * i]) : make_float4(0.f, 0.f, 0.f, 0.f);

    float d0 = 0.f, n0 = 0.f, d1 = 0.f, n1 = 0.f;
    #pragma unroll
    for (int i = 0; i < 4; i++) {
        float4 q = qs[lane + 32 * i];
        d0 += a[i].x * q.x + a[i].y * q.y + a[i].z * q.z + a[i].w * q.w;
        n0 += a[i].x * a[i].x + a[i].y * a[i].y + a[i].z * a[i].z + a[i].w * a[i].w;
        d1 += b[i].x * q.x + b[i].y * q.y + b[i].z * q.z + b[i].w * q.w;
        n1 += b[i].x * b[i].x + b[i].y * b[i].y + b[i].z * b[i].z + b[i].w * b[i].w;
    }
    #pragma unroll
    for (int o = 16; o > 0; o >>= 1) {
        d0 += __shfl_down_sync(0xffffffffu, d0, o);
        n0 += __shfl_down_sync(0xffffffffu, n0, o);
        d1 += __shfl_down_sync(0xffffffffu, d1, o);
        n1 += __shfl_down_sync(0xffffffffu, n1, o);
    }
    if (lane == 0) {
        float s0 = d0 / fmaxf(sqrtf(n0), EPSF);
        g_sims[r0] = s0;
        atomicAdd(&g_hist[mono(s0) >> 16], 1);
        if (has1) {
            float s1 = d1 / fmaxf(sqrtf(n1), EPSF);
            g_sims[r0 + 1] = s1;
            atomicAdd(&g_hist[mono(s1) >> 16], 1);
        }
    }
}

// ---- K3: parallel suffix-scan of 65536 bins (1 block, 1024 threads) ---------
// Thread t owns bins [t*64, t*64+64). Finds largest bin b whose suffix sum >= k.
__global__ void __launch_bounds__(1024) k_scan(const int* topk) {
    __shared__ int warpTot[32];
    __shared__ int warpSfx[33];

    int k = topk ? *topk : 100;
    if (k < 1) k = 1;

    int t    = threadIdx.x;
    int lane = t & 31;
    int w    = t >> 5;

    // local sum of 64 bins via 16 int4 loads
    const int4* h4 = reinterpret_cast<const int4*>(g_hist);
    int local = 0;
    #pragma unroll
    for (int i = 0; i < 16; i++) {
        int4 v = h4[t * 16 + i];
        local += v.x + v.y + v.z + v.w;
    }

    // warp inclusive suffix scan (descending thread index)
    int s = local;
    #pragma unroll
    for (int o = 1; o < 32; o <<= 1) {
        int u = __shfl_down_sync(0xffffffffu, s, o);
        if (lane + o < 32) s += u;
    }
    if (lane == 0) warpTot[w] = s;
    __syncthreads();

    if (w == 0) {
        int ws = warpTot[lane];
        #pragma unroll
        for (int o = 1; o < 32; o <<= 1) {
            int u = __shfl_down_sync(0xffffffffu, ws, o);
            if (lane + o < 32) ws += u;
        }
        warpSfx[lane] = ws;
        if (lane == 0) warpSfx[32] = 0;
    }
    __syncthreads();

    // count strictly above thread t's bins
    int above = (s - local) + warpSfx[w + 1];

    if (above < k && above + local >= k) {
        // crossing bin is inside this thread's 64 bins; walk from the top
        int cum = above;
        for (int j = 63; j >= 0; --j) {
            cum += g_hist[t * 64 + j];
            if (cum >= k) {
                g_thresh = ((unsigned)(t * 64 + j)) << 16;
                break;
            }
        }
    }
}

// ---- K4: gather survivors; last block performs exact rank selection --------
__global__ void __launch_bounds__(256) k_gather_final(int N, const int* topk,
                                                      float* __restrict__ out,
                                                      int out_size) {
    unsigned th = g_thresh;
    for (int i = blockIdx.x * 256 + threadIdx.x; i < N; i += gridDim.x * 256) {
        float v = g_sims[i];
        unsigned key = mono(v);
        if (key >= th) {
            int p = atomicAdd(&g_counter, 1);
            if (p < CAP) {
                g_candKey[p] = key;
                g_candIdx[p] = i;
                g_candVal[p] = v;
            }
        }
    }

    // last-block-done: the final block to finish does the k-selection
    __shared__ int s_last;
    __threadfence();
    __syncthreads();
    if (threadIdx.x == 0)
        s_last = (atomicAdd(&g_done, 1) == (int)gridDim.x - 1);
    __syncthreads();
    if (!s_last) return;

    __shared__ unsigned sk[CAP];
    __shared__ int      si[CAP];
    int n = g_counter;
    if (n > CAP) n = CAP;
    int k = topk ? *topk : 100;

    for (int i = threadIdx.x; i < n; i += 256) {
        sk[i] = g_candKey[i];
        si[i] = g_candIdx[i];
    }
    __syncthreads();

    for (int i = threadIdx.x; i < n; i += 256) {
        unsigned mk = sk[i];
        int      mi = si[i];
        int r = 0;
        for (int j = 0; j < n; j++) {
            unsigned kj = sk[j];
            r += (kj > mk) || (kj == mk && si[j] < mi);
        }
        if (r < k) {
            if (r < out_size)     out[r]     = g_candVal[i];
            if (k + r < out_size) out[k + r] = (float)si[i];
        }
    }
}

// ---------------------------------------------------------------------------
extern "C" void kernel_launch(void* const* d_in, const int* in_sizes, int n_in,
                              void* d_out, int out_size) {
    const float* q    = (const float*)d_in[0];
    const float* db   = (const float*)d_in[1];
    const int*   topk = (n_in >= 3) ? (const int*)d_in[2] : nullptr;

    int D = in_sizes[0];               // 512
    int N = in_sizes[1] / D;           // 500000
    if (N > MAXN) N = MAXN;

    k_init<<<64, 512>>>(q, D);

    // 2 rows per warp, 16 warps per block -> 32 rows per block
    int blocks = (N + 31) / 32;
    k_sims<<<blocks, 512>>>(db, N);

    k_scan<<<1, 1024>>>(topk);
    k_gather_final<<<512, 256>>>(N, topk, (float*)d_out, out_size);
}